// round 4
// baseline (speedup 1.0000x reference)
#include <cuda_runtime.h>
#include <cuda_bf16.h>

#define T_LEN 4096
#define N_DIM 256
#define U_DIM 128
#define K_DIM 32
#define P_DIM 128
#define NK    8192   // N_DIM * K_DIM
#define CH_L  64     // chunk length
#define NCH   64     // number of chunks (T_LEN / CH_L)
#define G_T   16     // timesteps per k1 CTA

// ---------------- device scratch (no runtime allocation allowed) ----------------
__device__ float g_S_re[(size_t)T_LEN * NK];   // 134 MB
__device__ float g_S_im[(size_t)T_LEN * NK];   // 134 MB
__device__ float g_send_re[NCH * NK];
__device__ float g_send_im[NCH * NK];
__device__ float g_carry_re[NCH * NK];
__device__ float g_carry_im[NCH * NK];
__device__ float g_apow_re[CH_L * NK];
__device__ float g_apow_im[CH_L * NK];
// k1 B weights pre-packed as m16n8k16 A-fragments (hi/lo bf16)
__device__ unsigned int g_Wfrag[2 * 16 * 8 * 2 * 32 * 4];
// k3 fused weight matrix W[p, j] (j = 640: Cre | -Cim | D) as A-fragments:
// uint4 index = ((mt*40 + s)*2 + hl)*32 + lane
__device__ uint4 g_W3[8 * 40 * 2 * 32];

typedef unsigned long long u64;
typedef unsigned int u32;

// ---------------- bf16 helpers ----------------
__device__ __forceinline__ u32 pack_bf16(float lo, float hi) {   // lo -> bits[0:16)
    __nv_bfloat16 a = __float2bfloat16_rn(lo), b = __float2bfloat16_rn(hi);
    unsigned short ua = *(unsigned short*)&a, ub = *(unsigned short*)&b;
    return (u32)ua | ((u32)ub << 16);
}
__device__ __forceinline__ float bf16_hi(float f) {
    return __bfloat162float(__float2bfloat16_rn(f));
}

// mma.sync m16n8k16 row.col f32.bf16.bf16.f32
__device__ __forceinline__ void mma16816(float* c, const u32* a, const u32* b) {
    asm volatile(
        "mma.sync.aligned.m16n8k16.row.col.f32.bf16.bf16.f32 "
        "{%0,%1,%2,%3}, {%4,%5,%6,%7}, {%8,%9}, {%0,%1,%2,%3};"
        : "+f"(c[0]), "+f"(c[1]), "+f"(c[2]), "+f"(c[3])
        : "r"(a[0]), "r"(a[1]), "r"(a[2]), "r"(a[3]), "r"(b[0]), "r"(b[1]));
}

// ---------------- K0a: pack k1 B weights into A-fragment layout (hi + lo) ------
__global__ __launch_bounds__(256) void k0_pack(
    const float* __restrict__ Bre, const float* __restrict__ Bim)
{
    int t = blockIdx.x * 256 + threadIdx.x;
    int r    = t & 3;
    int lane = (t >> 2) & 31;
    int s    = (t >> 7) & 7;
    int mt   = (t >> 10) & 15;
    int h    = t >> 14;
    int g = lane >> 2, c = lane & 3;
    int n = mt * 16 + g + ((r & 1) ? 8 : 0);
    int u = s * 16 + 2 * c + ((r & 2) ? 8 : 0);
    const float* W = h ? Bim : Bre;
    float f0 = W[n * U_DIM + u];
    float f1 = W[n * U_DIM + u + 1];
    float h0 = bf16_hi(f0), l0 = f0 - h0;
    float h1 = bf16_hi(f1), l1 = f1 - h1;
    int base = h * 32768 + ((mt * 8 + s) * 2) * 128 + lane * 4 + r;
    g_Wfrag[base]       = pack_bf16(h0, h1);   // hl = 0
    g_Wfrag[base + 128] = pack_bf16(l0, l1);   // hl = 1
}

// ---------------- K0b: pack k3 fused weights [Cre | -Cim | D] ------------------
// 20480 uint4 slots; thread per slot.
__global__ __launch_bounds__(256) void k0_pack3(
    const float* __restrict__ Cre, const float* __restrict__ Cim,
    const float* __restrict__ D)
{
    int t = blockIdx.x * 256 + threadIdx.x;
    if (t >= 20480) return;
    int lane = t & 31;
    int q = t >> 5;
    int hl = q & 1; q >>= 1;
    int s = q % 40;
    int mt = q / 40;
    int g = lane >> 2, c = lane & 3;
    u32 o[4];
#pragma unroll
    for (int r = 0; r < 4; r++) {
        int prow = mt * 16 + g + ((r & 1) ? 8 : 0);
        int jc = s * 16 + 2 * c + ((r & 2) ? 8 : 0);
        float f0, f1;
        if (s < 16) {
            f0 = Cre[prow * N_DIM + jc];
            f1 = Cre[prow * N_DIM + jc + 1];
        } else if (s < 32) {
            f0 = -Cim[prow * N_DIM + (jc - 256)];
            f1 = -Cim[prow * N_DIM + (jc - 256) + 1];
        } else {
            f0 = D[prow * U_DIM + (jc - 512)];
            f1 = D[prow * U_DIM + (jc - 512) + 1];
        }
        float h0 = bf16_hi(f0), h1 = bf16_hi(f1);
        o[r] = hl ? pack_bf16(f0 - h0, f1 - h1) : pack_bf16(h0, h1);
    }
    g_W3[t] = make_uint4(o[0], o[1], o[2], o[3]);
}

// ---------------- K1 (HMMA): S[t,n,k] = sum_u B[n,u] * x[t,u,k] ----------------
__global__ __launch_bounds__(256) void k1_mma(const float* __restrict__ x)
{
    extern __shared__ char sm[];
    float* Xs = (float*)sm;                          // [128][33] padded: 16896 B
    u32*   Wf = (u32*)(sm + 16896);                  // 32768 u32 = 131072 B
    u64*   Xf = (u64*)(sm + 16896 + 131072);         // 2048 u64 = 16384 B

    int tid = threadIdx.x;
    int w = tid >> 5, lane = tid & 31;
    int half = blockIdx.x;
    float* dst = half ? g_S_im : g_S_re;
    int t0 = blockIdx.y * G_T;

    {
        const float4* src = (const float4*)(g_Wfrag + half * 32768);
        float4* d4 = (float4*)Wf;
#pragma unroll
        for (int i = 0; i < 32; i++) d4[tid + i * 256] = src[tid + i * 256];
    }

    int g = lane >> 2, c = lane & 3;

    for (int tt = 0; tt < G_T; tt++) {
        int t = t0 + tt;
        __syncthreads();
        const float* xp = x + (size_t)t * (U_DIM * K_DIM);
#pragma unroll
        for (int i = 0; i < 16; i++) {
            int e = tid + i * 256;
            Xs[(e >> 5) * 33 + (e & 31)] = xp[e];
        }
        __syncthreads();
#pragma unroll
        for (int i = 0; i < 8; i++) {
            int slot = tid + i * 256;
            int sl = slot & 31;
            int hl = (slot >> 5) & 1;
            int nt = (slot >> 6) & 3;
            int s  = slot >> 8;
            int sg = sl >> 2, sc = sl & 3;
            int u0 = s * 16 + 2 * sc;
            int kc = nt * 8 + sg;
            float v0 = Xs[u0 * 33 + kc];
            float v1 = Xs[(u0 + 1) * 33 + kc];
            float v2 = Xs[(u0 + 8) * 33 + kc];
            float v3 = Xs[(u0 + 9) * 33 + kc];
            u32 b0, b1;
            if (hl == 0) {
                b0 = pack_bf16(bf16_hi(v0), bf16_hi(v1));
                b1 = pack_bf16(bf16_hi(v2), bf16_hi(v3));
            } else {
                b0 = pack_bf16(v0 - bf16_hi(v0), v1 - bf16_hi(v1));
                b1 = pack_bf16(v2 - bf16_hi(v2), v3 - bf16_hi(v3));
            }
            u64 pv;
            asm("mov.b64 %0, {%1, %2};" : "=l"(pv) : "r"(b0), "r"(b1));
            Xf[slot] = pv;
        }
        __syncthreads();
        float acc[2][4][4];
#pragma unroll
        for (int mtl = 0; mtl < 2; mtl++)
#pragma unroll
            for (int nt = 0; nt < 4; nt++)
#pragma unroll
                for (int q = 0; q < 4; q++) acc[mtl][nt][q] = 0.f;

        for (int s = 0; s < 8; s++) {
            u32 ah[2][4], al[2][4];
#pragma unroll
            for (int mtl = 0; mtl < 2; mtl++) {
                int mt = w * 2 + mtl;
                const uint4* ap = (const uint4*)(Wf + ((mt * 8 + s) * 2) * 128);
                uint4 vh = ap[lane];
                uint4 vl = ap[32 + lane];
                ah[mtl][0] = vh.x; ah[mtl][1] = vh.y; ah[mtl][2] = vh.z; ah[mtl][3] = vh.w;
                al[mtl][0] = vl.x; al[mtl][1] = vl.y; al[mtl][2] = vl.z; al[mtl][3] = vl.w;
            }
            u32 bh[4][2], bl[4][2];
#pragma unroll
            for (int nt = 0; nt < 4; nt++) {
                u64 vh = Xf[((s * 4 + nt) * 2 + 0) * 32 + lane];
                u64 vl = Xf[((s * 4 + nt) * 2 + 1) * 32 + lane];
                asm("mov.b64 {%0, %1}, %2;" : "=r"(bh[nt][0]), "=r"(bh[nt][1]) : "l"(vh));
                asm("mov.b64 {%0, %1}, %2;" : "=r"(bl[nt][0]), "=r"(bl[nt][1]) : "l"(vl));
            }
#pragma unroll
            for (int mtl = 0; mtl < 2; mtl++)
#pragma unroll
                for (int nt = 0; nt < 4; nt++) {
                    mma16816(acc[mtl][nt], ah[mtl], bh[nt]);
                    mma16816(acc[mtl][nt], ah[mtl], bl[nt]);
                    mma16816(acc[mtl][nt], al[mtl], bh[nt]);
                }
        }
        size_t tb = (size_t)t * NK;
#pragma unroll
        for (int mtl = 0; mtl < 2; mtl++) {
            int nrow = (w * 2 + mtl) * 16 + g;
#pragma unroll
            for (int nt = 0; nt < 4; nt++) {
                int kc = nt * 8 + 2 * c;
                float2 lo = make_float2(acc[mtl][nt][0], acc[mtl][nt][1]);
                float2 hi = make_float2(acc[mtl][nt][2], acc[mtl][nt][3]);
                *(float2*)(dst + tb + nrow * K_DIM + kc) = lo;
                *(float2*)(dst + tb + (nrow + 8) * K_DIM + kc) = hi;
            }
        }
    }
}

// ---------------- K2a: local (per-chunk) scans, in place -----------------------
__global__ __launch_bounds__(256) void k2_local(
    const float* __restrict__ Are, const float* __restrict__ Aim)
{
    int c = blockIdx.x * 256 + threadIdx.x;
    int chunk = blockIdx.y;
    float ar = Are[c], ai = Aim[c];
    float sr = 0.f, si = 0.f;
    int base = chunk * CH_L * NK + c;
    for (int tg = 0; tg < CH_L; tg += 4) {
        float inr[4], ini[4];
#pragma unroll
        for (int j = 0; j < 4; j++) {
            inr[j] = g_S_re[base + j * NK];
            ini[j] = g_S_im[base + j * NK];
        }
#pragma unroll
        for (int j = 0; j < 4; j++) {
            float nr = fmaf(ar, sr, fmaf(-ai, si, inr[j]));
            float ni = fmaf(ar, si, fmaf(ai, sr, ini[j]));
            sr = nr; si = ni;
            g_S_re[base + j * NK] = sr;
            g_S_im[base + j * NK] = si;
        }
        base += 4 * NK;
    }
    g_send_re[chunk * NK + c] = sr;
    g_send_im[chunk * NK + c] = si;
}

// ---------------- K2b: power table + cross-chunk carries (prefetched) ----------
__global__ __launch_bounds__(256) void k2_carry(
    const float* __restrict__ Are, const float* __restrict__ Aim)
{
    int c = blockIdx.x * 256 + threadIdx.x;
    float ar = Are[c], ai = Aim[c];
    float qr = ar, qi = ai;
    float a64r = 0.f, a64i = 0.f;
    for (int j = 0; j < CH_L; j++) {
        g_apow_re[j * NK + c] = qr;
        g_apow_im[j * NK + c] = qi;
        if (j == CH_L - 1) { a64r = qr; a64i = qi; }
        float tmp = qr * ar - qi * ai;
        qi = qr * ai + qi * ar;
        qr = tmp;
    }
    float cr = 0.f, ci = 0.f;
    for (int ch = 0; ch < NCH; ch += 8) {
        float sr[8], si[8];
#pragma unroll
        for (int j = 0; j < 8; j++) {
            sr[j] = g_send_re[(ch + j) * NK + c];
            si[j] = g_send_im[(ch + j) * NK + c];
        }
#pragma unroll
        for (int j = 0; j < 8; j++) {
            g_carry_re[(ch + j) * NK + c] = cr;
            g_carry_im[(ch + j) * NK + c] = ci;
            float tmp = fmaf(a64r, cr, fmaf(-a64i, ci, sr[j]));
            ci = fmaf(a64r, ci, fmaf(a64i, cr, si[j]));
            cr = tmp;
        }
    }
}

// ---------------- K3 (HMMA): out[p, (t,k)] = W[p,j] * V[j,(t,k)], fixup fused --
// block = 4 timesteps; 8 warps; warp w = m-tile (p rows 16w..16w+15).
// Reduction j = 640: [Cre * fixed_re (s 0..15) | -Cim * fixed_im (16..31) | D * x (32..39)]
__global__ __launch_bounds__(256) void k3_mma(
    const float* __restrict__ x, float* __restrict__ out)
{
    __shared__ float Vs[16 * 132];      // V tile: 16 j-rows x 128 cols (pad 132)
    __shared__ u64 Xf[2][1024];         // B-fragments double buffer

    int tid = threadIdx.x;
    int w = tid >> 5, lane = tid & 31;
    int t0 = blockIdx.x * 4;
    int chunk = t0 >> 6, tl0 = t0 & 63;

    // staging decomposition: thread -> (j, tl, kb)
    int j  = tid >> 4;            // 0..15
    int rr = tid & 15;
    int tl = rr >> 2;             // 0..3
    int kb = (rr & 3) * 8;        // 0,8,16,24
    size_t sb_t = (size_t)(t0 + tl) * NK;
    int colb = tl * 32 + kb;
    float* vdst = &Vs[j * 132 + colb];

    // ---- stage s-step into Vs (fixup fused for state parts)
    auto stage = [&](int s) {
        if (s < 32) {
            const float* src = (s < 16) ? g_S_re : g_S_im;
            int n0 = (s & 15) * 16;
            int ro = (n0 + j) * 32 + kb;
            float lv[8], prv[8], piv[8], crv[8], civ[8];
            *(float4*)lv        = *(const float4*)(src + sb_t + ro);
            *(float4*)(lv + 4)  = *(const float4*)(src + sb_t + ro + 4);
            int po = (tl0 + tl) * NK + ro;
            *(float4*)prv       = *(const float4*)(g_apow_re + po);
            *(float4*)(prv + 4) = *(const float4*)(g_apow_re + po + 4);
            *(float4*)piv       = *(const float4*)(g_apow_im + po);
            *(float4*)(piv + 4) = *(const float4*)(g_apow_im + po + 4);
            int co = chunk * NK + ro;
            *(float4*)crv       = *(const float4*)(g_carry_re + co);
            *(float4*)(crv + 4) = *(const float4*)(g_carry_re + co + 4);
            *(float4*)civ       = *(const float4*)(g_carry_im + co);
            *(float4*)(civ + 4) = *(const float4*)(g_carry_im + co + 4);
            float o[8];
            if (s < 16) {
#pragma unroll
                for (int q = 0; q < 8; q++)
                    o[q] = fmaf(prv[q], crv[q], fmaf(-piv[q], civ[q], lv[q]));
            } else {
#pragma unroll
                for (int q = 0; q < 8; q++)
                    o[q] = fmaf(prv[q], civ[q], fmaf(piv[q], crv[q], lv[q]));
            }
            *(float4*)vdst       = *(float4*)o;
            *(float4*)(vdst + 4) = *(float4*)(o + 4);
        } else {
            int u0 = (s - 32) * 16;
            const float* xp = x + (size_t)(t0 + tl) * (U_DIM * K_DIM) + (u0 + j) * K_DIM + kb;
            *(float4*)vdst       = *(const float4*)xp;
            *(float4*)(vdst + 4) = *(const float4*)(xp + 4);
        }
    };

    float acc[16][4];
#pragma unroll
    for (int nt = 0; nt < 16; nt++)
#pragma unroll
        for (int q = 0; q < 4; q++) acc[nt][q] = 0.f;

    stage(0);
    __syncthreads();

    for (int s = 0; s < 40; s++) {
        // ---- build B-fragments for this s from Vs
        int buf = s & 1;
#pragma unroll
        for (int i = 0; i < 4; i++) {
            int slot = tid + i * 256;
            int sl = slot & 31;
            int hl = (slot >> 5) & 1;
            int nt = slot >> 6;
            int sg = sl >> 2, sc = sl & 3;
            int col = nt * 8 + sg;
            float v0 = Vs[(2 * sc) * 132 + col];
            float v1 = Vs[(2 * sc + 1) * 132 + col];
            float v2 = Vs[(2 * sc + 8) * 132 + col];
            float v3 = Vs[(2 * sc + 9) * 132 + col];
            u32 b0, b1;
            if (hl == 0) {
                b0 = pack_bf16(bf16_hi(v0), bf16_hi(v1));
                b1 = pack_bf16(bf16_hi(v2), bf16_hi(v3));
            } else {
                b0 = pack_bf16(v0 - bf16_hi(v0), v1 - bf16_hi(v1));
                b1 = pack_bf16(v2 - bf16_hi(v2), v3 - bf16_hi(v3));
            }
            u64 pv;
            asm("mov.b64 %0, {%1, %2};" : "=l"(pv) : "r"(b0), "r"(b1));
            Xf[buf][slot] = pv;
        }
        __syncthreads();
        // ---- prefetch next stage (writes Vs; build of this s is done)
        if (s < 39) stage(s + 1);
        // ---- MMA for this s
        {
            const uint4* wp = g_W3 + ((w * 40 + s) * 2) * 32;
            uint4 vh = wp[lane];
            uint4 vl = wp[32 + lane];
            u32 ah[4] = {vh.x, vh.y, vh.z, vh.w};
            u32 al[4] = {vl.x, vl.y, vl.z, vl.w};
#pragma unroll
            for (int nt = 0; nt < 16; nt++) {
                u64 h64 = Xf[buf][nt * 64 + lane];
                u64 l64 = Xf[buf][nt * 64 + 32 + lane];
                u32 bh[2], bl[2];
                asm("mov.b64 {%0, %1}, %2;" : "=r"(bh[0]), "=r"(bh[1]) : "l"(h64));
                asm("mov.b64 {%0, %1}, %2;" : "=r"(bl[0]), "=r"(bl[1]) : "l"(l64));
                mma16816(acc[nt], ah, bh);
                mma16816(acc[nt], ah, bl);
                mma16816(acc[nt], al, bh);
            }
        }
        __syncthreads();
    }

    // ---- epilogue
    int g_ = lane >> 2, c_ = lane & 3;
#pragma unroll
    for (int nt = 0; nt < 16; nt++) {
        int col = nt * 8 + 2 * c_;
        int t = t0 + (col >> 5);
        int k = col & 31;
        int p = w * 16 + g_;
        *(float2*)(out + (size_t)t * (P_DIM * K_DIM) + p * K_DIM + k) =
            make_float2(acc[nt][0], acc[nt][1]);
        *(float2*)(out + (size_t)t * (P_DIM * K_DIM) + (p + 8) * K_DIM + k) =
            make_float2(acc[nt][2], acc[nt][3]);
    }
}

// ---------------- launch ----------------
extern "C" void kernel_launch(void* const* d_in, const int* in_sizes, int n_in,
                              void* d_out, int out_size)
{
    const float* x   = (const float*)d_in[0];
    const float* Are = (const float*)d_in[1];
    const float* Aim = (const float*)d_in[2];
    const float* Bre = (const float*)d_in[3];
    const float* Bim = (const float*)d_in[4];
    const float* Cre = (const float*)d_in[5];
    const float* Cim = (const float*)d_in[6];
    const float* D   = (const float*)d_in[7];
    float* out = (float*)d_out;

    k0_pack<<<128, 256>>>(Bre, Bim);
    k0_pack3<<<80, 256>>>(Cre, Cim, D);

    cudaFuncSetAttribute(k1_mma, cudaFuncAttributeMaxDynamicSharedMemorySize, 164352);
    k1_mma<<<dim3(2, T_LEN / G_T), 256, 164352>>>(x);

    dim3 g2(NK / 256, NCH);
    k2_local<<<g2, 256>>>(Are, Aim);
    k2_carry<<<NK / 256, 256>>>(Are, Aim);

    k3_mma<<<T_LEN / 4, 256>>>(x, out);
}

// round 5
// speedup vs baseline: 2.3078x; 2.3078x over previous
#include <cuda_runtime.h>
#include <cuda_fp16.h>

#define T_LEN 4096
#define N_DIM 256
#define U_DIM 128
#define K_DIM 32
#define P_DIM 128
#define NK    8192   // N_DIM * K_DIM
#define CH_L  64     // chunk length
#define NCH   64     // number of chunks (T_LEN / CH_L)
#define G_T   16     // timesteps per k1 CTA

// ---------------- device scratch (no runtime allocation allowed) ----------------
__device__ float g_S_re[(size_t)T_LEN * NK];   // 134 MB
__device__ float g_S_im[(size_t)T_LEN * NK];   // 134 MB
__device__ float g_send_re[NCH * NK];
__device__ float g_send_im[NCH * NK];
__device__ float g_carry_re[NCH * NK];
__device__ float g_carry_im[NCH * NK];
__device__ float g_apow_re[CH_L * NK];
__device__ float g_apow_im[CH_L * NK];
// k1 B weights as m16n8k16 A-fragments, single fp16:
// u32 index = (h*16 + mt)*8*128 + s*128 + lane*4 + r
__device__ unsigned int g_Wfrag[2 * 16 * 8 * 128];
// k3 fused weight matrix W[p, j] (j = 640: Cre | -Cim | D) as fp16 A-fragments:
// uint4 index = (mt*40 + s)*32 + lane
__device__ uint4 g_W3[8 * 40 * 32];

typedef unsigned long long u64;
typedef unsigned int u32;

// ---------------- fp16 helpers ----------------
__device__ __forceinline__ u32 pack_h2(float lo, float hi) {   // lo -> bits[0:16)
    __half2 h = __floats2half2_rn(lo, hi);
    return *(u32*)&h;
}

// mma.sync m16n8k16 row.col f32.f16.f16.f32
__device__ __forceinline__ void mma16816h(float* c, const u32* a, const u32* b) {
    asm volatile(
        "mma.sync.aligned.m16n8k16.row.col.f32.f16.f16.f32 "
        "{%0,%1,%2,%3}, {%4,%5,%6,%7}, {%8,%9}, {%0,%1,%2,%3};"
        : "+f"(c[0]), "+f"(c[1]), "+f"(c[2]), "+f"(c[3])
        : "r"(a[0]), "r"(a[1]), "r"(a[2]), "r"(a[3]), "r"(b[0]), "r"(b[1]));
}

// ---------------- K0a: pack k1 B weights into A-fragment layout (fp16) ---------
// work item = (h, mt, s, lane, r): 2*16*8*32*4 = 32768
__global__ __launch_bounds__(256) void k0_pack(
    const float* __restrict__ Bre, const float* __restrict__ Bim)
{
    int t = blockIdx.x * 256 + threadIdx.x;
    int r    = t & 3;
    int lane = (t >> 2) & 31;
    int s    = (t >> 7) & 7;
    int mt   = (t >> 10) & 15;
    int h    = t >> 14;
    int g = lane >> 2, c = lane & 3;
    int n = mt * 16 + g + ((r & 1) ? 8 : 0);
    int u = s * 16 + 2 * c + ((r & 2) ? 8 : 0);
    const float* W = h ? Bim : Bre;
    float f0 = W[n * U_DIM + u];
    float f1 = W[n * U_DIM + u + 1];
    g_Wfrag[(h * 16 + mt) * 1024 + s * 128 + lane * 4 + r] = pack_h2(f0, f1);
}

// ---------------- K0b: pack k3 fused weights [Cre | -Cim | D] (fp16) -----------
// 10240 uint4 slots; thread per slot.
__global__ __launch_bounds__(256) void k0_pack3(
    const float* __restrict__ Cre, const float* __restrict__ Cim,
    const float* __restrict__ D)
{
    int t = blockIdx.x * 256 + threadIdx.x;
    if (t >= 10240) return;
    int lane = t & 31;
    int q = t >> 5;
    int s = q % 40;
    int mt = q / 40;
    int g = lane >> 2, c = lane & 3;
    u32 o[4];
#pragma unroll
    for (int r = 0; r < 4; r++) {
        int prow = mt * 16 + g + ((r & 1) ? 8 : 0);
        int jc = s * 16 + 2 * c + ((r & 2) ? 8 : 0);
        float f0, f1;
        if (s < 16) {
            f0 = Cre[prow * N_DIM + jc];
            f1 = Cre[prow * N_DIM + jc + 1];
        } else if (s < 32) {
            f0 = -Cim[prow * N_DIM + (jc - 256)];
            f1 = -Cim[prow * N_DIM + (jc - 256) + 1];
        } else {
            f0 = D[prow * U_DIM + (jc - 512)];
            f1 = D[prow * U_DIM + (jc - 512) + 1];
        }
        o[r] = pack_h2(f0, f1);
    }
    g_W3[t] = make_uint4(o[0], o[1], o[2], o[3]);
}

// ---------------- K1 (HMMA fp16): S[t,n,k] = sum_u B[n,u] * x[t,u,k] -----------
// grid = (2 halves: re/im) x (T_LEN/G_T). CTA 256 threads (8 warps).
// warp w owns m-tiles {2w, 2w+1}.
__global__ __launch_bounds__(256) void k1_mma(const float* __restrict__ x)
{
    extern __shared__ char sm[];
    float* Xs = (float*)sm;                          // [128][33] padded: 16896 B
    u32*   Wf = (u32*)(sm + 16896);                  // 16384 u32 = 65536 B
    u64*   Xf = (u64*)(sm + 16896 + 65536);          // 1024 u64 = 8192 B

    int tid = threadIdx.x;
    int w = tid >> 5, lane = tid & 31;
    int half = blockIdx.x;
    float* dst = half ? g_S_im : g_S_re;
    int t0 = blockIdx.y * G_T;

    // copy this half's weight fragments to smem (4096 uint4)
    {
        const float4* src = (const float4*)(g_Wfrag + half * 16384);
        float4* d4 = (float4*)Wf;
#pragma unroll
        for (int i = 0; i < 16; i++) d4[tid + i * 256] = src[tid + i * 256];
    }

    int g = lane >> 2, c = lane & 3;

    for (int tt = 0; tt < G_T; tt++) {
        int t = t0 + tt;
        __syncthreads();   // protect Xs/Xf from previous iteration's readers
        // ---- stage x[t] into padded smem (coalesced)
        const float* xp = x + (size_t)t * (U_DIM * K_DIM);
#pragma unroll
        for (int i = 0; i < 16; i++) {
            int e = tid + i * 256;
            Xs[(e >> 5) * 33 + (e & 31)] = xp[e];
        }
        __syncthreads();
        // ---- convert into fp16 B-fragments: 4 slots per thread (1024 total)
#pragma unroll
        for (int i = 0; i < 4; i++) {
            int slot = tid + i * 256;
            int sl = slot & 31;
            int nt = (slot >> 5) & 3;
            int s  = slot >> 7;
            int sg = sl >> 2, sc = sl & 3;
            int u0 = s * 16 + 2 * sc;
            int kc = nt * 8 + sg;
            float v0 = Xs[u0 * 33 + kc];
            float v1 = Xs[(u0 + 1) * 33 + kc];
            float v2 = Xs[(u0 + 8) * 33 + kc];
            float v3 = Xs[(u0 + 9) * 33 + kc];
            u32 b0 = pack_h2(v0, v1);
            u32 b1 = pack_h2(v2, v3);
            u64 pv;
            asm("mov.b64 %0, {%1, %2};" : "=l"(pv) : "r"(b0), "r"(b1));
            Xf[slot] = pv;
        }
        __syncthreads();
        // ---- HMMA mainloop (single pass)
        float acc[2][4][4];
#pragma unroll
        for (int mtl = 0; mtl < 2; mtl++)
#pragma unroll
            for (int nt = 0; nt < 4; nt++)
#pragma unroll
                for (int q = 0; q < 4; q++) acc[mtl][nt][q] = 0.f;

#pragma unroll
        for (int s = 0; s < 8; s++) {
            u32 a[2][4];
#pragma unroll
            for (int mtl = 0; mtl < 2; mtl++) {
                int mt = w * 2 + mtl;
                const uint4* ap = (const uint4*)(Wf + mt * 1024 + s * 128);
                uint4 v = ap[lane];
                a[mtl][0] = v.x; a[mtl][1] = v.y; a[mtl][2] = v.z; a[mtl][3] = v.w;
            }
#pragma unroll
            for (int nt = 0; nt < 4; nt++) {
                u64 bv = Xf[(s * 4 + nt) * 32 + lane];
                u32 b[2];
                asm("mov.b64 {%0, %1}, %2;" : "=r"(b[0]), "=r"(b[1]) : "l"(bv));
#pragma unroll
                for (int mtl = 0; mtl < 2; mtl++)
                    mma16816h(acc[mtl][nt], a[mtl], b);
            }
        }
        // ---- epilogue: write fp32 states
        size_t tb = (size_t)t * NK;
#pragma unroll
        for (int mtl = 0; mtl < 2; mtl++) {
            int nrow = (w * 2 + mtl) * 16 + g;
#pragma unroll
            for (int nt = 0; nt < 4; nt++) {
                int kc = nt * 8 + 2 * c;
                float2 lo = make_float2(acc[mtl][nt][0], acc[mtl][nt][1]);
                float2 hi = make_float2(acc[mtl][nt][2], acc[mtl][nt][3]);
                *(float2*)(dst + tb + nrow * K_DIM + kc) = lo;
                *(float2*)(dst + tb + (nrow + 8) * K_DIM + kc) = hi;
            }
        }
    }
}

// ---------------- K2a: local (per-chunk) scans, in place -----------------------
__global__ __launch_bounds__(256) void k2_local(
    const float* __restrict__ Are, const float* __restrict__ Aim)
{
    int c = blockIdx.x * 256 + threadIdx.x;
    int chunk = blockIdx.y;
    float ar = Are[c], ai = Aim[c];
    float sr = 0.f, si = 0.f;
    int base = chunk * CH_L * NK + c;
    for (int tg = 0; tg < CH_L; tg += 4) {
        float inr[4], ini[4];
#pragma unroll
        for (int j = 0; j < 4; j++) {
            inr[j] = g_S_re[base + j * NK];
            ini[j] = g_S_im[base + j * NK];
        }
#pragma unroll
        for (int j = 0; j < 4; j++) {
            float nr = fmaf(ar, sr, fmaf(-ai, si, inr[j]));
            float ni = fmaf(ar, si, fmaf(ai, sr, ini[j]));
            sr = nr; si = ni;
            g_S_re[base + j * NK] = sr;
            g_S_im[base + j * NK] = si;
        }
        base += 4 * NK;
    }
    g_send_re[chunk * NK + c] = sr;
    g_send_im[chunk * NK + c] = si;
}

// ---------------- K2b: power table + cross-chunk carries (prefetched) ----------
__global__ __launch_bounds__(256) void k2_carry(
    const float* __restrict__ Are, const float* __restrict__ Aim)
{
    int c = blockIdx.x * 256 + threadIdx.x;
    float ar = Are[c], ai = Aim[c];
    float qr = ar, qi = ai;
    float a64r = 0.f, a64i = 0.f;
    for (int j = 0; j < CH_L; j++) {
        g_apow_re[j * NK + c] = qr;
        g_apow_im[j * NK + c] = qi;
        if (j == CH_L - 1) { a64r = qr; a64i = qi; }
        float tmp = qr * ar - qi * ai;
        qi = qr * ai + qi * ar;
        qr = tmp;
    }
    float cr = 0.f, ci = 0.f;
    for (int ch = 0; ch < NCH; ch += 8) {
        float sr[8], si[8];
#pragma unroll
        for (int j = 0; j < 8; j++) {
            sr[j] = g_send_re[(ch + j) * NK + c];
            si[j] = g_send_im[(ch + j) * NK + c];
        }
#pragma unroll
        for (int j = 0; j < 8; j++) {
            g_carry_re[(ch + j) * NK + c] = cr;
            g_carry_im[(ch + j) * NK + c] = ci;
            float tmp = fmaf(a64r, cr, fmaf(-a64i, ci, sr[j]));
            ci = fmaf(a64r, ci, fmaf(a64i, cr, si[j]));
            cr = tmp;
        }
    }
}

// ---------------- K3 (HMMA fp16): out[p,(t,k)] = W[p,j] * V[j,(t,k)], fixup fused
// block = 4 timesteps; 8 warps; warp w = m-tile (p rows 16w..16w+15).
// Reduction j = 640: [Cre*fixed_re (s 0..15) | -Cim*fixed_im (16..31) | D*x (32..39)]
__global__ __launch_bounds__(256) void k3_mma(
    const float* __restrict__ x, float* __restrict__ out)
{
    __shared__ float Vs[16 * 132];      // V tile: 16 j-rows x 128 cols (pad 132)
    __shared__ u64 Xf[2][512];          // fp16 B-fragments double buffer

    int tid = threadIdx.x;
    int w = tid >> 5, lane = tid & 31;
    int t0 = blockIdx.x * 4;
    int chunk = t0 >> 6, tl0 = t0 & 63;

    // staging decomposition: thread -> (j, tl, kb)
    int j  = tid >> 4;            // 0..15
    int rr = tid & 15;
    int tl = rr >> 2;             // 0..3
    int kb = (rr & 3) * 8;        // 0,8,16,24
    size_t sb_t = (size_t)(t0 + tl) * NK;
    int colb = tl * 32 + kb;
    float* vdst = &Vs[j * 132 + colb];

    // ---- stage s-step into Vs (fixup fused for state parts)
    auto stage = [&](int s) {
        if (s < 32) {
            const float* src = (s < 16) ? g_S_re : g_S_im;
            int n0 = (s & 15) * 16;
            int ro = (n0 + j) * 32 + kb;
            float lv[8], prv[8], piv[8], crv[8], civ[8];
            *(float4*)lv        = *(const float4*)(src + sb_t + ro);
            *(float4*)(lv + 4)  = *(const float4*)(src + sb_t + ro + 4);
            int po = (tl0 + tl) * NK + ro;
            *(float4*)prv       = *(const float4*)(g_apow_re + po);
            *(float4*)(prv + 4) = *(const float4*)(g_apow_re + po + 4);
            *(float4*)piv       = *(const float4*)(g_apow_im + po);
            *(float4*)(piv + 4) = *(const float4*)(g_apow_im + po + 4);
            int co = chunk * NK + ro;
            *(float4*)crv       = *(const float4*)(g_carry_re + co);
            *(float4*)(crv + 4) = *(const float4*)(g_carry_re + co + 4);
            *(float4*)civ       = *(const float4*)(g_carry_im + co);
            *(float4*)(civ + 4) = *(const float4*)(g_carry_im + co + 4);
            float o[8];
            if (s < 16) {
#pragma unroll
                for (int q = 0; q < 8; q++)
                    o[q] = fmaf(prv[q], crv[q], fmaf(-piv[q], civ[q], lv[q]));
            } else {
#pragma unroll
                for (int q = 0; q < 8; q++)
                    o[q] = fmaf(prv[q], civ[q], fmaf(piv[q], crv[q], lv[q]));
            }
            *(float4*)vdst       = *(float4*)o;
            *(float4*)(vdst + 4) = *(float4*)(o + 4);
        } else {
            int u0 = (s - 32) * 16;
            const float* xp = x + (size_t)(t0 + tl) * (U_DIM * K_DIM) + (u0 + j) * K_DIM + kb;
            *(float4*)vdst       = *(const float4*)xp;
            *(float4*)(vdst + 4) = *(const float4*)(xp + 4);
        }
    };

    float acc[16][4];
#pragma unroll
    for (int nt = 0; nt < 16; nt++)
#pragma unroll
        for (int q = 0; q < 4; q++) acc[nt][q] = 0.f;

    stage(0);
    __syncthreads();

    for (int s = 0; s < 40; s++) {
        int buf = s & 1;
        // ---- build fp16 B-fragments for this s from Vs (2 slots/thread)
#pragma unroll
        for (int i = 0; i < 2; i++) {
            int slot = tid + i * 256;
            int sl = slot & 31;
            int nt = slot >> 5;            // 0..15
            int sg = sl >> 2, sc = sl & 3;
            int col = nt * 8 + sg;
            float v0 = Vs[(2 * sc) * 132 + col];
            float v1 = Vs[(2 * sc + 1) * 132 + col];
            float v2 = Vs[(2 * sc + 8) * 132 + col];
            float v3 = Vs[(2 * sc + 9) * 132 + col];
            u32 b0 = pack_h2(v0, v1);
            u32 b1 = pack_h2(v2, v3);
            u64 pv;
            asm("mov.b64 %0, {%1, %2};" : "=l"(pv) : "r"(b0), "r"(b1));
            Xf[buf][slot] = pv;
        }
        __syncthreads();
        // ---- prefetch next stage (writes Vs; build of this s is done)
        if (s < 39) stage(s + 1);
        // ---- MMA for this s (single pass)
        {
            const uint4* wp = g_W3 + (w * 40 + s) * 32;
            uint4 v = wp[lane];
            u32 a[4] = {v.x, v.y, v.z, v.w};
#pragma unroll
            for (int nt = 0; nt < 16; nt++) {
                u64 bv = Xf[buf][nt * 32 + lane];
                u32 b[2];
                asm("mov.b64 {%0, %1}, %2;" : "=r"(b[0]), "=r"(b[1]) : "l"(bv));
                mma16816h(acc[nt], a, b);
            }
        }
        __syncthreads();
    }

    // ---- epilogue
    int g_ = lane >> 2, c_ = lane & 3;
#pragma unroll
    for (int nt = 0; nt < 16; nt++) {
        int col = nt * 8 + 2 * c_;
        int t = t0 + (col >> 5);
        int k = col & 31;
        int p = w * 16 + g_;
        *(float2*)(out + (size_t)t * (P_DIM * K_DIM) + p * K_DIM + k) =
            make_float2(acc[nt][0], acc[nt][1]);
        *(float2*)(out + (size_t)t * (P_DIM * K_DIM) + (p + 8) * K_DIM + k) =
            make_float2(acc[nt][2], acc[nt][3]);
    }
}

// ---------------- launch ----------------
extern "C" void kernel_launch(void* const* d_in, const int* in_sizes, int n_in,
                              void* d_out, int out_size)
{
    const float* x   = (const float*)d_in[0];
    const float* Are = (const float*)d_in[1];
    const float* Aim = (const float*)d_in[2];
    const float* Bre = (const float*)d_in[3];
    const float* Bim = (const float*)d_in[4];
    const float* Cre = (const float*)d_in[5];
    const float* Cim = (const float*)d_in[6];
    const float* D   = (const float*)d_in[7];
    float* out = (float*)d_out;

    k0_pack<<<128, 256>>>(Bre, Bim);
    k0_pack3<<<40, 256>>>(Cre, Cim, D);

    cudaFuncSetAttribute(k1_mma, cudaFuncAttributeMaxDynamicSharedMemorySize, 90624);
    k1_mma<<<dim3(2, T_LEN / G_T), 256, 90624>>>(x);

    dim3 g2(NK / 256, NCH);
    k2_local<<<g2, 256>>>(Are, Aim);
    k2_carry<<<NK / 256, 256>>>(Are, Aim);

    k3_mma<<<T_LEN / 4, 256>>>(x, out);
}

// round 6
// speedup vs baseline: 2.5951x; 1.1245x over previous
#include <cuda_runtime.h>
#include <cuda_fp16.h>

#define T_LEN 4096
#define N_DIM 256
#define U_DIM 128
#define K_DIM 32
#define P_DIM 128
#define NK    8192   // N_DIM * K_DIM
#define CH_L  64     // chunk length
#define NCH   64     // number of chunks (T_LEN / CH_L)
#define G_T   16     // timesteps per k1 CTA

// ---------------- device scratch (no runtime allocation allowed) ----------------
__device__ __half g_S_re[(size_t)T_LEN * NK];   // 67 MB (fp16)
__device__ __half g_S_im[(size_t)T_LEN * NK];   // 67 MB (fp16)
__device__ float g_send_re[NCH * NK];
__device__ float g_send_im[NCH * NK];
__device__ float g_carry_re[NCH * NK];
__device__ float g_carry_im[NCH * NK];
__device__ float g_apow_re[CH_L * NK];
__device__ float g_apow_im[CH_L * NK];
// k1 B weights as m16n8k16 A-fragments, single fp16:
// u32 index = (h*16 + mt)*8*128 + s*128 + lane*4 + r
__device__ unsigned int g_Wfrag[2 * 16 * 8 * 128];
// k3 fused weight matrix W[p, j] (j = 640: Cre | -Cim | D) as fp16 A-fragments:
// uint4 index = (mt*40 + s)*32 + lane
__device__ uint4 g_W3[8 * 40 * 32];

typedef unsigned long long u64;
typedef unsigned int u32;

// ---------------- fp16 helpers ----------------
__device__ __forceinline__ u32 pack_h2(float lo, float hi) {   // lo -> bits[0:16)
    __half2 h = __floats2half2_rn(lo, hi);
    return *(u32*)&h;
}
__device__ __forceinline__ float2 unpack_h2(u32 v) {
    __half2 h = *(__half2*)&v;
    return __half22float2(h);
}

// mma.sync m16n8k16 row.col f32.f16.f16.f32
__device__ __forceinline__ void mma16816h(float* c, const u32* a, const u32* b) {
    asm volatile(
        "mma.sync.aligned.m16n8k16.row.col.f32.f16.f16.f32 "
        "{%0,%1,%2,%3}, {%4,%5,%6,%7}, {%8,%9}, {%0,%1,%2,%3};"
        : "+f"(c[0]), "+f"(c[1]), "+f"(c[2]), "+f"(c[3])
        : "r"(a[0]), "r"(a[1]), "r"(a[2]), "r"(a[3]), "r"(b[0]), "r"(b[1]));
}

// ---------------- K0a: pack k1 B weights into A-fragment layout (fp16) ---------
__global__ __launch_bounds__(256) void k0_pack(
    const float* __restrict__ Bre, const float* __restrict__ Bim)
{
    int t = blockIdx.x * 256 + threadIdx.x;
    int r    = t & 3;
    int lane = (t >> 2) & 31;
    int s    = (t >> 7) & 7;
    int mt   = (t >> 10) & 15;
    int h    = t >> 14;
    int g = lane >> 2, c = lane & 3;
    int n = mt * 16 + g + ((r & 1) ? 8 : 0);
    int u = s * 16 + 2 * c + ((r & 2) ? 8 : 0);
    const float* W = h ? Bim : Bre;
    float f0 = W[n * U_DIM + u];
    float f1 = W[n * U_DIM + u + 1];
    g_Wfrag[(h * 16 + mt) * 1024 + s * 128 + lane * 4 + r] = pack_h2(f0, f1);
}

// ---------------- K0b: pack k3 fused weights [Cre | -Cim | D] (fp16) -----------
__global__ __launch_bounds__(256) void k0_pack3(
    const float* __restrict__ Cre, const float* __restrict__ Cim,
    const float* __restrict__ D)
{
    int t = blockIdx.x * 256 + threadIdx.x;
    if (t >= 10240) return;
    int lane = t & 31;
    int q = t >> 5;
    int s = q % 40;
    int mt = q / 40;
    int g = lane >> 2, c = lane & 3;
    u32 o[4];
#pragma unroll
    for (int r = 0; r < 4; r++) {
        int prow = mt * 16 + g + ((r & 1) ? 8 : 0);
        int jc = s * 16 + 2 * c + ((r & 2) ? 8 : 0);
        float f0, f1;
        if (s < 16) {
            f0 = Cre[prow * N_DIM + jc];
            f1 = Cre[prow * N_DIM + jc + 1];
        } else if (s < 32) {
            f0 = -Cim[prow * N_DIM + (jc - 256)];
            f1 = -Cim[prow * N_DIM + (jc - 256) + 1];
        } else {
            f0 = D[prow * U_DIM + (jc - 512)];
            f1 = D[prow * U_DIM + (jc - 512) + 1];
        }
        o[r] = pack_h2(f0, f1);
    }
    g_W3[t] = make_uint4(o[0], o[1], o[2], o[3]);
}

// ---------------- K1 (HMMA fp16): S[t,n,k] = sum_u B[n,u] * x[t,u,k] -----------
__global__ __launch_bounds__(256) void k1_mma(const float* __restrict__ x)
{
    extern __shared__ char sm[];
    float* Xs = (float*)sm;                          // [128][33] padded: 16896 B
    u32*   Wf = (u32*)(sm + 16896);                  // 16384 u32 = 65536 B
    u64*   Xf = (u64*)(sm + 16896 + 65536);          // 1024 u64 = 8192 B

    int tid = threadIdx.x;
    int w = tid >> 5, lane = tid & 31;
    int half = blockIdx.x;
    __half* dst = half ? g_S_im : g_S_re;
    int t0 = blockIdx.y * G_T;

    {
        const float4* src = (const float4*)(g_Wfrag + half * 16384);
        float4* d4 = (float4*)Wf;
#pragma unroll
        for (int i = 0; i < 16; i++) d4[tid + i * 256] = src[tid + i * 256];
    }

    int g = lane >> 2, c = lane & 3;

    for (int tt = 0; tt < G_T; tt++) {
        int t = t0 + tt;
        __syncthreads();
        const float* xp = x + (size_t)t * (U_DIM * K_DIM);
#pragma unroll
        for (int i = 0; i < 16; i++) {
            int e = tid + i * 256;
            Xs[(e >> 5) * 33 + (e & 31)] = xp[e];
        }
        __syncthreads();
#pragma unroll
        for (int i = 0; i < 4; i++) {
            int slot = tid + i * 256;
            int sl = slot & 31;
            int nt = (slot >> 5) & 3;
            int s  = slot >> 7;
            int sg = sl >> 2, sc = sl & 3;
            int u0 = s * 16 + 2 * sc;
            int kc = nt * 8 + sg;
            float v0 = Xs[u0 * 33 + kc];
            float v1 = Xs[(u0 + 1) * 33 + kc];
            float v2 = Xs[(u0 + 8) * 33 + kc];
            float v3 = Xs[(u0 + 9) * 33 + kc];
            u32 b0 = pack_h2(v0, v1);
            u32 b1 = pack_h2(v2, v3);
            u64 pv;
            asm("mov.b64 %0, {%1, %2};" : "=l"(pv) : "r"(b0), "r"(b1));
            Xf[slot] = pv;
        }
        __syncthreads();
        float acc[2][4][4];
#pragma unroll
        for (int mtl = 0; mtl < 2; mtl++)
#pragma unroll
            for (int nt = 0; nt < 4; nt++)
#pragma unroll
                for (int q = 0; q < 4; q++) acc[mtl][nt][q] = 0.f;

#pragma unroll
        for (int s = 0; s < 8; s++) {
            u32 a[2][4];
#pragma unroll
            for (int mtl = 0; mtl < 2; mtl++) {
                int mt = w * 2 + mtl;
                const uint4* ap = (const uint4*)(Wf + mt * 1024 + s * 128);
                uint4 v = ap[lane];
                a[mtl][0] = v.x; a[mtl][1] = v.y; a[mtl][2] = v.z; a[mtl][3] = v.w;
            }
#pragma unroll
            for (int nt = 0; nt < 4; nt++) {
                u64 bv = Xf[(s * 4 + nt) * 32 + lane];
                u32 b[2];
                asm("mov.b64 {%0, %1}, %2;" : "=r"(b[0]), "=r"(b[1]) : "l"(bv));
#pragma unroll
                for (int mtl = 0; mtl < 2; mtl++)
                    mma16816h(acc[mtl][nt], a[mtl], b);
            }
        }
        // ---- epilogue: write fp16 states (packed pairs along k)
        size_t tb = (size_t)t * NK;
#pragma unroll
        for (int mtl = 0; mtl < 2; mtl++) {
            int nrow = (w * 2 + mtl) * 16 + g;
#pragma unroll
            for (int nt = 0; nt < 4; nt++) {
                int kc = nt * 8 + 2 * c;
                *(u32*)&dst[tb + nrow * K_DIM + kc] = pack_h2(acc[mtl][nt][0], acc[mtl][nt][1]);
                *(u32*)&dst[tb + (nrow + 8) * K_DIM + kc] = pack_h2(acc[mtl][nt][2], acc[mtl][nt][3]);
            }
        }
    }
}

// ---------------- K2a: local (per-chunk) scans, in place (fp16 storage) --------
// thread = 2 adjacent chains; fp32 scan state in registers.
__global__ __launch_bounds__(256) void k2_local(
    const float* __restrict__ Are, const float* __restrict__ Aim)
{
    int c2 = (blockIdx.x * 256 + threadIdx.x) * 2;   // chain pair
    int chunk = blockIdx.y;
    float2 arv = *(const float2*)&Are[c2];
    float2 aiv = *(const float2*)&Aim[c2];
    float sr0 = 0.f, si0 = 0.f, sr1 = 0.f, si1 = 0.f;
    size_t base = (size_t)chunk * CH_L * NK + c2;
    for (int tg = 0; tg < CH_L; tg += 4) {
        u32 vr[4], vi[4];
#pragma unroll
        for (int j = 0; j < 4; j++) {
            vr[j] = *(const u32*)&g_S_re[base + (size_t)j * NK];
            vi[j] = *(const u32*)&g_S_im[base + (size_t)j * NK];
        }
#pragma unroll
        for (int j = 0; j < 4; j++) {
            float2 inr = unpack_h2(vr[j]);
            float2 ini = unpack_h2(vi[j]);
            float nr0 = fmaf(arv.x, sr0, fmaf(-aiv.x, si0, inr.x));
            float ni0 = fmaf(arv.x, si0, fmaf(aiv.x, sr0, ini.x));
            float nr1 = fmaf(arv.y, sr1, fmaf(-aiv.y, si1, inr.y));
            float ni1 = fmaf(arv.y, si1, fmaf(aiv.y, sr1, ini.y));
            sr0 = nr0; si0 = ni0; sr1 = nr1; si1 = ni1;
            *(u32*)&g_S_re[base + (size_t)j * NK] = pack_h2(sr0, sr1);
            *(u32*)&g_S_im[base + (size_t)j * NK] = pack_h2(si0, si1);
        }
        base += (size_t)4 * NK;
    }
    g_send_re[chunk * NK + c2] = sr0;
    g_send_re[chunk * NK + c2 + 1] = sr1;
    g_send_im[chunk * NK + c2] = si0;
    g_send_im[chunk * NK + c2 + 1] = si1;
}

// ---------------- K2b: power table + cross-chunk carries (prefetched) ----------
__global__ __launch_bounds__(256) void k2_carry(
    const float* __restrict__ Are, const float* __restrict__ Aim)
{
    int c = blockIdx.x * 256 + threadIdx.x;
    float ar = Are[c], ai = Aim[c];
    float qr = ar, qi = ai;
    float a64r = 0.f, a64i = 0.f;
    for (int j = 0; j < CH_L; j++) {
        g_apow_re[j * NK + c] = qr;
        g_apow_im[j * NK + c] = qi;
        if (j == CH_L - 1) { a64r = qr; a64i = qi; }
        float tmp = qr * ar - qi * ai;
        qi = qr * ai + qi * ar;
        qr = tmp;
    }
    float cr = 0.f, ci = 0.f;
    for (int ch = 0; ch < NCH; ch += 8) {
        float sr[8], si[8];
#pragma unroll
        for (int j = 0; j < 8; j++) {
            sr[j] = g_send_re[(ch + j) * NK + c];
            si[j] = g_send_im[(ch + j) * NK + c];
        }
#pragma unroll
        for (int j = 0; j < 8; j++) {
            g_carry_re[(ch + j) * NK + c] = cr;
            g_carry_im[(ch + j) * NK + c] = ci;
            float tmp = fmaf(a64r, cr, fmaf(-a64i, ci, sr[j]));
            ci = fmaf(a64r, ci, fmaf(a64i, cr, si[j]));
            cr = tmp;
        }
    }
}

// ---------------- K3 (HMMA fp16): out[p,(t,k)] = W[p,j] * V[j,(t,k)], fixup fused
__global__ __launch_bounds__(256) void k3_mma(
    const float* __restrict__ x, float* __restrict__ out)
{
    __shared__ float Vs[16 * 132];      // V tile: 16 j-rows x 128 cols (pad 132)
    __shared__ u64 Xf[2][512];          // fp16 B-fragments double buffer

    int tid = threadIdx.x;
    int w = tid >> 5, lane = tid & 31;
    int t0 = blockIdx.x * 4;
    int chunk = t0 >> 6, tl0 = t0 & 63;

    int j  = tid >> 4;            // 0..15
    int rr = tid & 15;
    int tl = rr >> 2;             // 0..3
    int kb = (rr & 3) * 8;        // 0,8,16,24
    size_t sb_t = (size_t)(t0 + tl) * NK;
    int colb = tl * 32 + kb;
    float* vdst = &Vs[j * 132 + colb];

    auto stage = [&](int s) {
        if (s < 32) {
            const __half* src = (s < 16) ? g_S_re : g_S_im;
            int n0 = (s & 15) * 16;
            int ro = (n0 + j) * 32 + kb;
            uint4 hv = *(const uint4*)&src[sb_t + ro];   // 8 halves
            float lv[8];
            {
                float2 p0 = unpack_h2(hv.x), p1 = unpack_h2(hv.y);
                float2 p2 = unpack_h2(hv.z), p3 = unpack_h2(hv.w);
                lv[0] = p0.x; lv[1] = p0.y; lv[2] = p1.x; lv[3] = p1.y;
                lv[4] = p2.x; lv[5] = p2.y; lv[6] = p3.x; lv[7] = p3.y;
            }
            float prv[8], piv[8], crv[8], civ[8];
            int po = (tl0 + tl) * NK + ro;
            *(float4*)prv       = *(const float4*)(g_apow_re + po);
            *(float4*)(prv + 4) = *(const float4*)(g_apow_re + po + 4);
            *(float4*)piv       = *(const float4*)(g_apow_im + po);
            *(float4*)(piv + 4) = *(const float4*)(g_apow_im + po + 4);
            int co = chunk * NK + ro;
            *(float4*)crv       = *(const float4*)(g_carry_re + co);
            *(float4*)(crv + 4) = *(const float4*)(g_carry_re + co + 4);
            *(float4*)civ       = *(const float4*)(g_carry_im + co);
            *(float4*)(civ + 4) = *(const float4*)(g_carry_im + co + 4);
            float o[8];
            if (s < 16) {
#pragma unroll
                for (int q = 0; q < 8; q++)
                    o[q] = fmaf(prv[q], crv[q], fmaf(-piv[q], civ[q], lv[q]));
            } else {
#pragma unroll
                for (int q = 0; q < 8; q++)
                    o[q] = fmaf(prv[q], civ[q], fmaf(piv[q], crv[q], lv[q]));
            }
            *(float4*)vdst       = *(float4*)o;
            *(float4*)(vdst + 4) = *(float4*)(o + 4);
        } else {
            int u0 = (s - 32) * 16;
            const float* xp = x + (size_t)(t0 + tl) * (U_DIM * K_DIM) + (u0 + j) * K_DIM + kb;
            *(float4*)vdst       = *(const float4*)xp;
            *(float4*)(vdst + 4) = *(const float4*)(xp + 4);
        }
    };

    float acc[16][4];
#pragma unroll
    for (int nt = 0; nt < 16; nt++)
#pragma unroll
        for (int q = 0; q < 4; q++) acc[nt][q] = 0.f;

    stage(0);
    __syncthreads();

    for (int s = 0; s < 40; s++) {
        int buf = s & 1;
#pragma unroll
        for (int i = 0; i < 2; i++) {
            int slot = tid + i * 256;
            int sl = slot & 31;
            int nt = slot >> 5;            // 0..15
            int sg = sl >> 2, sc = sl & 3;
            int col = nt * 8 + sg;
            float v0 = Vs[(2 * sc) * 132 + col];
            float v1 = Vs[(2 * sc + 1) * 132 + col];
            float v2 = Vs[(2 * sc + 8) * 132 + col];
            float v3 = Vs[(2 * sc + 9) * 132 + col];
            u32 b0 = pack_h2(v0, v1);
            u32 b1 = pack_h2(v2, v3);
            u64 pv;
            asm("mov.b64 %0, {%1, %2};" : "=l"(pv) : "r"(b0), "r"(b1));
            Xf[buf][slot] = pv;
        }
        __syncthreads();
        if (s < 39) stage(s + 1);
        {
            const uint4* wp = g_W3 + (w * 40 + s) * 32;
            uint4 v = wp[lane];
            u32 a[4] = {v.x, v.y, v.z, v.w};
#pragma unroll
            for (int nt = 0; nt < 16; nt++) {
                u64 bv = Xf[buf][nt * 32 + lane];
                u32 b[2];
                asm("mov.b64 {%0, %1}, %2;" : "=r"(b[0]), "=r"(b[1]) : "l"(bv));
                mma16816h(acc[nt], a, b);
            }
        }
        __syncthreads();
    }

    int g_ = lane >> 2, c_ = lane & 3;
#pragma unroll
    for (int nt = 0; nt < 16; nt++) {
        int col = nt * 8 + 2 * c_;
        int t = t0 + (col >> 5);
        int k = col & 31;
        int p = w * 16 + g_;
        *(float2*)(out + (size_t)t * (P_DIM * K_DIM) + p * K_DIM + k) =
            make_float2(acc[nt][0], acc[nt][1]);
        *(float2*)(out + (size_t)t * (P_DIM * K_DIM) + (p + 8) * K_DIM + k) =
            make_float2(acc[nt][2], acc[nt][3]);
    }
}

// ---------------- launch ----------------
extern "C" void kernel_launch(void* const* d_in, const int* in_sizes, int n_in,
                              void* d_out, int out_size)
{
    const float* x   = (const float*)d_in[0];
    const float* Are = (const float*)d_in[1];
    const float* Aim = (const float*)d_in[2];
    const float* Bre = (const float*)d_in[3];
    const float* Bim = (const float*)d_in[4];
    const float* Cre = (const float*)d_in[5];
    const float* Cim = (const float*)d_in[6];
    const float* D   = (const float*)d_in[7];
    float* out = (float*)d_out;

    k0_pack<<<128, 256>>>(Bre, Bim);
    k0_pack3<<<40, 256>>>(Cre, Cim, D);

    cudaFuncSetAttribute(k1_mma, cudaFuncAttributeMaxDynamicSharedMemorySize, 90624);
    k1_mma<<<dim3(2, T_LEN / G_T), 256, 90624>>>(x);

    dim3 g2(NK / 512, NCH);
    k2_local<<<g2, 256>>>(Are, Aim);
    k2_carry<<<NK / 256, 256>>>(Are, Aim);

    k3_mma<<<T_LEN / 4, 256>>>(x, out);
}

// round 7
// speedup vs baseline: 2.6975x; 1.0394x over previous
#include <cuda_runtime.h>
#include <cuda_fp16.h>

#define T_LEN 4096
#define N_DIM 256
#define U_DIM 128
#define K_DIM 32
#define P_DIM 128
#define NK    8192   // N_DIM * K_DIM
#define CH_L  64     // chunk length
#define NCH   64     // number of chunks (T_LEN / CH_L)
#define G_T   16     // timesteps per k1 CTA

typedef unsigned long long u64;
typedef unsigned int u32;

// ---------------- device scratch (no runtime allocation allowed) ----------------
__device__ __half g_S_re[(size_t)T_LEN * NK];   // 67 MB (fp16)
__device__ __half g_S_im[(size_t)T_LEN * NK];   // 67 MB (fp16)
__device__ float g_send_re[NCH * NK];
__device__ float g_send_im[NCH * NK];
__device__ float g_carry_re[NCH * NK];
__device__ float g_carry_im[NCH * NK];
__device__ float g_apow_re[CH_L * NK];
__device__ float g_apow_im[CH_L * NK];
// x pre-converted to fp16 B-fragments: per t, 1024 u64 slots
// slot = s*128 + nt*32 + lane; u64 = (b0 = h2(x[u0][kc], x[u0+1][kc]),
//                                     b1 = h2(x[u0+8][kc], x[u0+9][kc]))
// with sg=lane>>2, sc=lane&3, u0=s*16+2sc, kc=nt*8+sg
__device__ u64 g_Xf16[(size_t)T_LEN * 1024];    // 33.5 MB
// k1 B weights as m16n8k16 A-fragments (fp16):
__device__ u32 g_Wfrag[2 * 16 * 8 * 128];
// k3 fused weight matrix W[p, j] (j = 640: Cre | -Cim | D) as fp16 A-fragments:
__device__ uint4 g_W3[8 * 40 * 32];

// ---------------- fp16 helpers ----------------
__device__ __forceinline__ u32 pack_h2(float lo, float hi) {
    __half2 h = __floats2half2_rn(lo, hi);
    return *(u32*)&h;
}
__device__ __forceinline__ float2 unpack_h2(u32 v) {
    __half2 h = *(__half2*)&v;
    return __half22float2(h);
}

// mma.sync m16n8k16 row.col f32.f16.f16.f32
__device__ __forceinline__ void mma16816h(float* c, const u32* a, const u32* b) {
    asm volatile(
        "mma.sync.aligned.m16n8k16.row.col.f32.f16.f16.f32 "
        "{%0,%1,%2,%3}, {%4,%5,%6,%7}, {%8,%9}, {%0,%1,%2,%3};"
        : "+f"(c[0]), "+f"(c[1]), "+f"(c[2]), "+f"(c[3])
        : "r"(a[0]), "r"(a[1]), "r"(a[2]), "r"(a[3]), "r"(b[0]), "r"(b[1]));
}

// ---------------- K0a: pack k1 B weights into A-fragment layout (fp16) ---------
__global__ __launch_bounds__(256) void k0_pack(
    const float* __restrict__ Bre, const float* __restrict__ Bim)
{
    int t = blockIdx.x * 256 + threadIdx.x;
    int r    = t & 3;
    int lane = (t >> 2) & 31;
    int s    = (t >> 7) & 7;
    int mt   = (t >> 10) & 15;
    int h    = t >> 14;
    int g = lane >> 2, c = lane & 3;
    int n = mt * 16 + g + ((r & 1) ? 8 : 0);
    int u = s * 16 + 2 * c + ((r & 2) ? 8 : 0);
    const float* W = h ? Bim : Bre;
    float f0 = W[n * U_DIM + u];
    float f1 = W[n * U_DIM + u + 1];
    g_Wfrag[(h * 16 + mt) * 1024 + s * 128 + lane * 4 + r] = pack_h2(f0, f1);
}

// ---------------- K0b: pack k3 fused weights [Cre | -Cim | D] (fp16) -----------
__global__ __launch_bounds__(256) void k0_pack3(
    const float* __restrict__ Cre, const float* __restrict__ Cim,
    const float* __restrict__ D)
{
    int t = blockIdx.x * 256 + threadIdx.x;
    if (t >= 10240) return;
    int lane = t & 31;
    int q = t >> 5;
    int s = q % 40;
    int mt = q / 40;
    int g = lane >> 2, c = lane & 3;
    u32 o[4];
#pragma unroll
    for (int r = 0; r < 4; r++) {
        int prow = mt * 16 + g + ((r & 1) ? 8 : 0);
        int jc = s * 16 + 2 * c + ((r & 2) ? 8 : 0);
        float f0, f1;
        if (s < 16) {
            f0 = Cre[prow * N_DIM + jc];
            f1 = Cre[prow * N_DIM + jc + 1];
        } else if (s < 32) {
            f0 = -Cim[prow * N_DIM + (jc - 256)];
            f1 = -Cim[prow * N_DIM + (jc - 256) + 1];
        } else {
            f0 = D[prow * U_DIM + (jc - 512)];
            f1 = D[prow * U_DIM + (jc - 512) + 1];
        }
        o[r] = pack_h2(f0, f1);
    }
    g_W3[t] = make_uint4(o[0], o[1], o[2], o[3]);
}

// ---------------- K0c: pre-convert x into fp16 B-fragments ---------------------
// block handles 8 timesteps; per t: stage x coalesced -> smem, emit 1024 u64.
__global__ __launch_bounds__(256) void k0_xfrag(const float* __restrict__ x)
{
    __shared__ float Xs[128 * 33];
    int tid = threadIdx.x;
    int t0 = blockIdx.x * 8;
    for (int tt = 0; tt < 8; tt++) {
        int t = t0 + tt;
        __syncthreads();
        const float* xp = x + (size_t)t * (U_DIM * K_DIM);
#pragma unroll
        for (int i = 0; i < 16; i++) {
            int e = tid + i * 256;
            Xs[(e >> 5) * 33 + (e & 31)] = xp[e];
        }
        __syncthreads();
        u64* dst = g_Xf16 + (size_t)t * 1024;
#pragma unroll
        for (int i = 0; i < 4; i++) {
            int slot = tid + i * 256;
            int sl = slot & 31;
            int nt = (slot >> 5) & 3;
            int s  = slot >> 7;
            int sg = sl >> 2, sc = sl & 3;
            int u0 = s * 16 + 2 * sc;
            int kc = nt * 8 + sg;
            float v0 = Xs[u0 * 33 + kc];
            float v1 = Xs[(u0 + 1) * 33 + kc];
            float v2 = Xs[(u0 + 8) * 33 + kc];
            float v3 = Xs[(u0 + 9) * 33 + kc];
            u32 b0 = pack_h2(v0, v1);
            u32 b1 = pack_h2(v2, v3);
            u64 pv;
            asm("mov.b64 %0, {%1, %2};" : "=l"(pv) : "r"(b0), "r"(b1));
            dst[slot] = pv;
        }
    }
}

// ---------------- K1 (HMMA fp16): S[t,n,k] = sum_u B[n,u] * x[t,u,k] -----------
// A (weights) in smem; B fragments loaded directly from g_Xf16. No per-t syncs.
__global__ __launch_bounds__(256) void k1_mma()
{
    extern __shared__ u32 Wf[];   // 16384 u32 = 64 KB

    int tid = threadIdx.x;
    int w = tid >> 5, lane = tid & 31;
    int half = blockIdx.x;
    __half* dst = half ? g_S_im : g_S_re;
    int t0 = blockIdx.y * G_T;

    {
        const float4* src = (const float4*)(g_Wfrag + half * 16384);
        float4* d4 = (float4*)Wf;
#pragma unroll
        for (int i = 0; i < 16; i++) d4[tid + i * 256] = src[tid + i * 256];
    }
    __syncthreads();

    int g = lane >> 2, c = lane & 3;

    for (int tt = 0; tt < G_T; tt++) {
        int t = t0 + tt;
        const u64* xf = g_Xf16 + (size_t)t * 1024;

        float acc[2][4][4];
#pragma unroll
        for (int mtl = 0; mtl < 2; mtl++)
#pragma unroll
            for (int nt = 0; nt < 4; nt++)
#pragma unroll
                for (int q = 0; q < 4; q++) acc[mtl][nt][q] = 0.f;

#pragma unroll
        for (int s = 0; s < 8; s++) {
            u32 a[2][4];
#pragma unroll
            for (int mtl = 0; mtl < 2; mtl++) {
                int mt = w * 2 + mtl;
                const uint4* ap = (const uint4*)(Wf + mt * 1024 + s * 128);
                uint4 v = ap[lane];
                a[mtl][0] = v.x; a[mtl][1] = v.y; a[mtl][2] = v.z; a[mtl][3] = v.w;
            }
            u64 bv[4];
#pragma unroll
            for (int nt = 0; nt < 4; nt++) bv[nt] = xf[(s * 4 + nt) * 32 + lane];
#pragma unroll
            for (int nt = 0; nt < 4; nt++) {
                u32 b[2];
                asm("mov.b64 {%0, %1}, %2;" : "=r"(b[0]), "=r"(b[1]) : "l"(bv[nt]));
#pragma unroll
                for (int mtl = 0; mtl < 2; mtl++)
                    mma16816h(acc[mtl][nt], a[mtl], b);
            }
        }
        size_t tb = (size_t)t * NK;
#pragma unroll
        for (int mtl = 0; mtl < 2; mtl++) {
            int nrow = (w * 2 + mtl) * 16 + g;
#pragma unroll
            for (int nt = 0; nt < 4; nt++) {
                int kc = nt * 8 + 2 * c;
                *(u32*)&dst[tb + nrow * K_DIM + kc] = pack_h2(acc[mtl][nt][0], acc[mtl][nt][1]);
                *(u32*)&dst[tb + (nrow + 8) * K_DIM + kc] = pack_h2(acc[mtl][nt][2], acc[mtl][nt][3]);
            }
        }
    }
}

// ---------------- K2a: local (per-chunk) scans, in place (fp16 storage) --------
__global__ __launch_bounds__(256) void k2_local(
    const float* __restrict__ Are, const float* __restrict__ Aim)
{
    int c2 = (blockIdx.x * 256 + threadIdx.x) * 2;
    int chunk = blockIdx.y;
    float2 arv = *(const float2*)&Are[c2];
    float2 aiv = *(const float2*)&Aim[c2];
    float sr0 = 0.f, si0 = 0.f, sr1 = 0.f, si1 = 0.f;
    size_t base = (size_t)chunk * CH_L * NK + c2;
    for (int tg = 0; tg < CH_L; tg += 4) {
        u32 vr[4], vi[4];
#pragma unroll
        for (int j = 0; j < 4; j++) {
            vr[j] = *(const u32*)&g_S_re[base + (size_t)j * NK];
            vi[j] = *(const u32*)&g_S_im[base + (size_t)j * NK];
        }
#pragma unroll
        for (int j = 0; j < 4; j++) {
            float2 inr = unpack_h2(vr[j]);
            float2 ini = unpack_h2(vi[j]);
            float nr0 = fmaf(arv.x, sr0, fmaf(-aiv.x, si0, inr.x));
            float ni0 = fmaf(arv.x, si0, fmaf(aiv.x, sr0, ini.x));
            float nr1 = fmaf(arv.y, sr1, fmaf(-aiv.y, si1, inr.y));
            float ni1 = fmaf(arv.y, si1, fmaf(aiv.y, sr1, ini.y));
            sr0 = nr0; si0 = ni0; sr1 = nr1; si1 = ni1;
            *(u32*)&g_S_re[base + (size_t)j * NK] = pack_h2(sr0, sr1);
            *(u32*)&g_S_im[base + (size_t)j * NK] = pack_h2(si0, si1);
        }
        base += (size_t)4 * NK;
    }
    g_send_re[chunk * NK + c2] = sr0;
    g_send_re[chunk * NK + c2 + 1] = sr1;
    g_send_im[chunk * NK + c2] = si0;
    g_send_im[chunk * NK + c2 + 1] = si1;
}

// ---------------- K2b: power table + cross-chunk carries (prefetched) ----------
__global__ __launch_bounds__(256) void k2_carry(
    const float* __restrict__ Are, const float* __restrict__ Aim)
{
    int c = blockIdx.x * 256 + threadIdx.x;
    float ar = Are[c], ai = Aim[c];
    float qr = ar, qi = ai;
    float a64r = 0.f, a64i = 0.f;
    for (int j = 0; j < CH_L; j++) {
        g_apow_re[j * NK + c] = qr;
        g_apow_im[j * NK + c] = qi;
        if (j == CH_L - 1) { a64r = qr; a64i = qi; }
        float tmp = qr * ar - qi * ai;
        qi = qr * ai + qi * ar;
        qr = tmp;
    }
    float cr = 0.f, ci = 0.f;
    for (int ch = 0; ch < NCH; ch += 8) {
        float sr[8], si[8];
#pragma unroll
        for (int j = 0; j < 8; j++) {
            sr[j] = g_send_re[(ch + j) * NK + c];
            si[j] = g_send_im[(ch + j) * NK + c];
        }
#pragma unroll
        for (int j = 0; j < 8; j++) {
            g_carry_re[(ch + j) * NK + c] = cr;
            g_carry_im[(ch + j) * NK + c] = ci;
            float tmp = fmaf(a64r, cr, fmaf(-a64i, ci, sr[j]));
            ci = fmaf(a64r, ci, fmaf(a64i, cr, si[j]));
            cr = tmp;
        }
    }
}

// ---------------- K3 (HMMA fp16): out = W * V, fixup fused ---------------------
// 32 state s-steps (staged, double-buffered, 1 sync/step) + 8 direct-LDG x steps.
__global__ __launch_bounds__(256) void k3_mma(float* __restrict__ out)
{
    __shared__ float Vs[2][16 * 132];
    __shared__ u64 Xf[2][512];

    int tid = threadIdx.x;
    int w = tid >> 5, lane = tid & 31;
    int t0 = blockIdx.x * 4;
    int chunk = t0 >> 6, tl0 = t0 & 63;

    int j  = tid >> 4;            // 0..15
    int rr = tid & 15;
    int tl = rr >> 2;             // 0..3
    int kb = (rr & 3) * 8;
    size_t sb_t = (size_t)(t0 + tl) * NK;
    int colb = tl * 32 + kb;

    // stage state s-step (s < 32) into Vs[buf], fixup fused
    auto stage = [&](int s, int buf) {
        float* vdst = &Vs[buf][j * 132 + colb];
        const __half* src = (s < 16) ? g_S_re : g_S_im;
        int n0 = (s & 15) * 16;
        int ro = (n0 + j) * 32 + kb;
        uint4 hv = *(const uint4*)&src[sb_t + ro];
        float lv[8];
        {
            float2 p0 = unpack_h2(hv.x), p1 = unpack_h2(hv.y);
            float2 p2 = unpack_h2(hv.z), p3 = unpack_h2(hv.w);
            lv[0] = p0.x; lv[1] = p0.y; lv[2] = p1.x; lv[3] = p1.y;
            lv[4] = p2.x; lv[5] = p2.y; lv[6] = p3.x; lv[7] = p3.y;
        }
        float prv[8], piv[8], crv[8], civ[8];
        int po = (tl0 + tl) * NK + ro;
        *(float4*)prv       = *(const float4*)(g_apow_re + po);
        *(float4*)(prv + 4) = *(const float4*)(g_apow_re + po + 4);
        *(float4*)piv       = *(const float4*)(g_apow_im + po);
        *(float4*)(piv + 4) = *(const float4*)(g_apow_im + po + 4);
        int co = chunk * NK + ro;
        *(float4*)crv       = *(const float4*)(g_carry_re + co);
        *(float4*)(crv + 4) = *(const float4*)(g_carry_re + co + 4);
        *(float4*)civ       = *(const float4*)(g_carry_im + co);
        *(float4*)(civ + 4) = *(const float4*)(g_carry_im + co + 4);
        float o[8];
        if (s < 16) {
#pragma unroll
            for (int q = 0; q < 8; q++)
                o[q] = fmaf(prv[q], crv[q], fmaf(-piv[q], civ[q], lv[q]));
        } else {
#pragma unroll
            for (int q = 0; q < 8; q++)
                o[q] = fmaf(prv[q], civ[q], fmaf(piv[q], crv[q], lv[q]));
        }
        *(float4*)vdst       = *(float4*)o;
        *(float4*)(vdst + 4) = *(float4*)(o + 4);
    };

    float acc[16][4];
#pragma unroll
    for (int nt = 0; nt < 16; nt++)
#pragma unroll
        for (int q = 0; q < 4; q++) acc[nt][q] = 0.f;

    stage(0, 0);
    __syncthreads();

    for (int s = 0; s < 32; s++) {
        int b = s & 1;
        if (s < 31) stage(s + 1, b ^ 1);
        // build fp16 B-fragments from Vs[b]
#pragma unroll
        for (int i = 0; i < 2; i++) {
            int slot = tid + i * 256;
            int sl = slot & 31;
            int nt = slot >> 5;
            int sg = sl >> 2, sc = sl & 3;
            int col = nt * 8 + sg;
            float v0 = Vs[b][(2 * sc) * 132 + col];
            float v1 = Vs[b][(2 * sc + 1) * 132 + col];
            float v2 = Vs[b][(2 * sc + 8) * 132 + col];
            float v3 = Vs[b][(2 * sc + 9) * 132 + col];
            u32 b0 = pack_h2(v0, v1);
            u32 b1 = pack_h2(v2, v3);
            u64 pv;
            asm("mov.b64 %0, {%1, %2};" : "=l"(pv) : "r"(b0), "r"(b1));
            Xf[b][slot] = pv;
        }
        __syncthreads();
        {
            const uint4* wp = g_W3 + (w * 40 + s) * 32;
            uint4 v = wp[lane];
            u32 a[4] = {v.x, v.y, v.z, v.w};
#pragma unroll
            for (int nt = 0; nt < 16; nt++) {
                u64 bv = Xf[b][nt * 32 + lane];
                u32 bb[2];
                asm("mov.b64 {%0, %1}, %2;" : "=r"(bb[0]), "=r"(bb[1]) : "l"(bv));
                mma16816h(acc[nt], a, bb);
            }
        }
    }

    // ---- D branch: x fragments direct from g_Xf16 (8 steps, no staging)
#pragma unroll
    for (int si = 0; si < 8; si++) {
        const uint4* wp = g_W3 + (w * 40 + 32 + si) * 32;
        uint4 v = wp[lane];
        u32 a[4] = {v.x, v.y, v.z, v.w};
        u64 bv[16];
#pragma unroll
        for (int nt = 0; nt < 16; nt++) {
            int tlx = nt >> 2, ntl = nt & 3;
            bv[nt] = g_Xf16[(size_t)(t0 + tlx) * 1024 + (si * 4 + ntl) * 32 + lane];
        }
#pragma unroll
        for (int nt = 0; nt < 16; nt++) {
            u32 bb[2];
            asm("mov.b64 {%0, %1}, %2;" : "=r"(bb[0]), "=r"(bb[1]) : "l"(bv[nt]));
            mma16816h(acc[nt], a, bb);
        }
    }

    // ---- epilogue
    int g_ = lane >> 2, c_ = lane & 3;
#pragma unroll
    for (int nt = 0; nt < 16; nt++) {
        int col = nt * 8 + 2 * c_;
        int t = t0 + (col >> 5);
        int k = col & 31;
        int p = w * 16 + g_;
        *(float2*)(out + (size_t)t * (P_DIM * K_DIM) + p * K_DIM + k) =
            make_float2(acc[nt][0], acc[nt][1]);
        *(float2*)(out + (size_t)t * (P_DIM * K_DIM) + (p + 8) * K_DIM + k) =
            make_float2(acc[nt][2], acc[nt][3]);
    }
}

// ---------------- launch ----------------
extern "C" void kernel_launch(void* const* d_in, const int* in_sizes, int n_in,
                              void* d_out, int out_size)
{
    const float* x   = (const float*)d_in[0];
    const float* Are = (const float*)d_in[1];
    const float* Aim = (const float*)d_in[2];
    const float* Bre = (const float*)d_in[3];
    const float* Bim = (const float*)d_in[4];
    const float* Cre = (const float*)d_in[5];
    const float* Cim = (const float*)d_in[6];
    const float* D   = (const float*)d_in[7];
    float* out = (float*)d_out;

    k0_pack<<<128, 256>>>(Bre, Bim);
    k0_pack3<<<40, 256>>>(Cre, Cim, D);
    k0_xfrag<<<512, 256>>>(x);

    cudaFuncSetAttribute(k1_mma, cudaFuncAttributeMaxDynamicSharedMemorySize, 65536);
    k1_mma<<<dim3(2, T_LEN / G_T), 256, 65536>>>();

    dim3 g2(NK / 512, NCH);
    k2_local<<<g2, 256>>>(Are, Aim);
    k2_carry<<<NK / 256, 256>>>(Are, Aim);

    k3_mma<<<T_LEN / 4, 256>>>(out);
}